// round 1
// baseline (speedup 1.0000x reference)
#include <cuda_runtime.h>
#include <math.h>

#define N_NODES 50000
#define E_EDGES 800000
#define E_TOT   (E_EDGES + N_NODES)
#define IN_DIM  512
#define F1      256
#define NH1     4
#define F2      40
#define NEG_SLOPE 0.2f
#define NINF (-__int_as_float(0x7f800000))

// ---------------- scratch (static device allocations only) ----------------
__device__ int   g_is64;
__device__ int   g_src[E_EDGES];
__device__ int   g_dst[E_EDGES];
__device__ int   g_deg[N_NODES];
__device__ int   g_rowstart[N_NODES + 1];
__device__ int   g_cursor[N_NODES];
__device__ int   g_csr[E_TOT];
__device__ float g_h1[(size_t)N_NODES * F1];
__device__ float g_as1[N_NODES * NH1];
__device__ float g_ad1[N_NODES * NH1];
__device__ float g_hmid[(size_t)N_NODES * F1];
__device__ float g_h2[(size_t)N_NODES * F2];
__device__ float g_as2[N_NODES];
__device__ float g_ad2[N_NODES];

// ---------------- helpers ----------------
__device__ __forceinline__ void atomicMaxFloatS(float* addr, float val) {
    if (val >= 0.f) atomicMax((int*)addr, __float_as_int(val));
    else            atomicMin((unsigned int*)addr, __float_as_uint(val));
}
__device__ __forceinline__ float lrelu(float x) { return x > 0.f ? x : NEG_SLOPE * x; }

// ---------------- edge dtype detect + convert ----------------
__global__ void k_detect(const int* e32) {
    int allzero = 1;
    for (int i = 1; i < 256; i += 2) if (e32[i] != 0) allzero = 0;
    g_is64 = allzero;
}

__global__ void k_convert(const void* eptr) {
    int i = blockIdx.x * blockDim.x + threadIdx.x;
    if (i >= E_EDGES) return;
    if (g_is64) {
        const long long* e = (const long long*)eptr;
        g_src[i] = (int)e[i];
        g_dst[i] = (int)e[E_EDGES + i];
    } else {
        const int* e = (const int*)eptr;
        g_src[i] = e[i];
        g_dst[i] = e[E_EDGES + i];
    }
}

__global__ void k_initdeg() {
    int i = blockIdx.x * blockDim.x + threadIdx.x;
    if (i < N_NODES) g_deg[i] = 1;  // self loop
}

__global__ void k_count() {
    int i = blockIdx.x * blockDim.x + threadIdx.x;
    if (i < E_EDGES) atomicAdd(&g_deg[g_dst[i]], 1);
}

// single-block exclusive scan over 50000 ints
__global__ void k_scan() {
    __shared__ int part[1024];
    const int t = threadIdx.x;
    const int CH = (N_NODES + 1023) / 1024;
    int lo = t * CH, hi = min(lo + CH, N_NODES);
    int s = 0;
    for (int i = lo; i < hi; i++) s += g_deg[i];
    part[t] = s;
    __syncthreads();
    for (int off = 1; off < 1024; off <<= 1) {
        int v = 0;
        if (t >= off) v = part[t - off];
        __syncthreads();
        part[t] += v;
        __syncthreads();
    }
    int run = (t > 0) ? part[t - 1] : 0;
    for (int i = lo; i < hi; i++) {
        g_rowstart[i] = run;
        g_cursor[i]   = run;
        run += g_deg[i];
    }
    if (t == 1023) g_rowstart[N_NODES] = part[1023];
}

__global__ void k_scatter() {
    int i = blockIdx.x * blockDim.x + threadIdx.x;
    if (i >= E_TOT) return;
    int s, d;
    if (i < E_EDGES) { s = g_src[i]; d = g_dst[i]; }
    else             { s = d = i - E_EDGES; }
    int pos = atomicAdd(&g_cursor[d], 1);
    g_csr[pos] = s;
}

// ---------------- GEMM1: h1 = x @ W1   [50000,512]x[512,256] ----------------
#define BM 128
#define BN 64
#define BK 32
__global__ __launch_bounds__(256) void k_gemm1(const float* __restrict__ x,
                                               const float* __restrict__ W) {
    __shared__ float As[BM][BK + 4];   // pad to 36 floats/row (144B, 16B aligned)
    __shared__ float Bs[BK][BN];
    const int bm = blockIdx.y * BM, bn = blockIdx.x * BN;
    const int t = threadIdx.x;
    const int tcol = (t & 15) * 4;     // 0..60
    const int trow = (t >> 4) * 8;     // 0..120
    float acc[8][4];
#pragma unroll
    for (int i = 0; i < 8; i++)
#pragma unroll
        for (int j = 0; j < 4; j++) acc[i][j] = 0.f;

    for (int k0 = 0; k0 < IN_DIM; k0 += BK) {
#pragma unroll
        for (int r = 0; r < 4; r++) {            // A: 1024 float4
            int f = t + r * 256;
            int row = f >> 3;
            int cv = (f & 7) * 4;
            float4 v = make_float4(0.f, 0.f, 0.f, 0.f);
            int gr = bm + row;
            if (gr < N_NODES) v = *(const float4*)&x[(size_t)gr * IN_DIM + k0 + cv];
            *(float4*)&As[row][cv] = v;
        }
#pragma unroll
        for (int r = 0; r < 2; r++) {            // B: 512 float4
            int f = t + r * 256;
            int row = f >> 4;
            int cv = (f & 15) * 4;
            *(float4*)&Bs[row][cv] = *(const float4*)&W[(size_t)(k0 + row) * F1 + bn + cv];
        }
        __syncthreads();
#pragma unroll
        for (int kk = 0; kk < BK; kk++) {
            float b[4];
            *(float4*)b = *(float4*)&Bs[kk][tcol];
            float a[8];
#pragma unroll
            for (int i = 0; i < 8; i++) a[i] = As[trow + i][kk];
#pragma unroll
            for (int i = 0; i < 8; i++)
#pragma unroll
                for (int j = 0; j < 4; j++) acc[i][j] = fmaf(a[i], b[j], acc[i][j]);
        }
        __syncthreads();
    }
#pragma unroll
    for (int i = 0; i < 8; i++) {
        int gr = bm + trow + i;
        if (gr < N_NODES)
            *(float4*)&g_h1[(size_t)gr * F1 + bn + tcol] =
                make_float4(acc[i][0], acc[i][1], acc[i][2], acc[i][3]);
    }
}

// ---------------- attention coefficients layer 1 (warp per node) ----------------
__global__ void k_asd1(const float* __restrict__ atts, const float* __restrict__ attd) {
    int node = blockIdx.x * 8 + (threadIdx.x >> 5);
    int lane = threadIdx.x & 31;
    if (node >= N_NODES) return;
    const float* hr = &g_h1[(size_t)node * F1];
    float4 h1v = *(const float4*)&hr[lane * 4];
    float4 h2v = *(const float4*)&hr[128 + lane * 4];
    float4 sa = *(const float4*)&atts[lane * 4];
    float4 sb = *(const float4*)&atts[128 + lane * 4];
    float4 da = *(const float4*)&attd[lane * 4];
    float4 db = *(const float4*)&attd[128 + lane * 4];
    float ps1 = h1v.x * sa.x + h1v.y * sa.y + h1v.z * sa.z + h1v.w * sa.w;
    float pd1 = h1v.x * da.x + h1v.y * da.y + h1v.z * da.z + h1v.w * da.w;
    float ps2 = h2v.x * sb.x + h2v.y * sb.y + h2v.z * sb.z + h2v.w * sb.w;
    float pd2 = h2v.x * db.x + h2v.y * db.y + h2v.z * db.z + h2v.w * db.w;
#pragma unroll
    for (int off = 8; off; off >>= 1) {
        ps1 += __shfl_down_sync(0xffffffffu, ps1, off);
        pd1 += __shfl_down_sync(0xffffffffu, pd1, off);
        ps2 += __shfl_down_sync(0xffffffffu, ps2, off);
        pd2 += __shfl_down_sync(0xffffffffu, pd2, off);
    }
    if (lane == 0) {   // heads 0 (first half) and 2 (second half)
        g_as1[node * 4 + 0] = ps1; g_ad1[node * 4 + 0] = pd1;
        g_as1[node * 4 + 2] = ps2; g_ad1[node * 4 + 2] = pd2;
    }
    if (lane == 16) {  // heads 1 and 3
        g_as1[node * 4 + 1] = ps1; g_ad1[node * 4 + 1] = pd1;
        g_as1[node * 4 + 3] = ps2; g_ad1[node * 4 + 3] = pd2;
    }
}

// ---------------- layer-1 aggregation: block per dst, fused bias+elu ----------------
#define CHUNK 512
__global__ __launch_bounds__(256) void k_agg1(const float* __restrict__ b1) {
    const int dst = blockIdx.x;
    const int t = threadIdx.x;
    const int start = g_rowstart[dst];
    const int end = g_rowstart[dst + 1];
    __shared__ float sm[NH1], ss[NH1];
    __shared__ float sal[CHUNK][NH1];
    __shared__ int   ssrc[CHUNK];
    float adv[NH1];
#pragma unroll
    for (int h = 0; h < NH1; h++) adv[h] = g_ad1[dst * 4 + h];
    if (t < NH1) { sm[t] = NINF; ss[t] = 0.f; }
    __syncthreads();

    // phase A1: per-head max
    float lm[NH1] = {NINF, NINF, NINF, NINF};
    for (int i = start + t; i < end; i += 256) {
        int s = g_csr[i];
#pragma unroll
        for (int h = 0; h < NH1; h++)
            lm[h] = fmaxf(lm[h], lrelu(g_as1[s * 4 + h] + adv[h]));
    }
#pragma unroll
    for (int h = 0; h < NH1; h++) atomicMaxFloatS(&sm[h], lm[h]);
    __syncthreads();
    float mx[NH1];
#pragma unroll
    for (int h = 0; h < NH1; h++) mx[h] = sm[h];

    // phase A2: per-head sum of exp
    float lsum[NH1] = {0.f, 0.f, 0.f, 0.f};
    for (int i = start + t; i < end; i += 256) {
        int s = g_csr[i];
#pragma unroll
        for (int h = 0; h < NH1; h++)
            lsum[h] += expf(lrelu(g_as1[s * 4 + h] + adv[h]) - mx[h]);
    }
#pragma unroll
    for (int h = 0; h < NH1; h++) atomicAdd(&ss[h], lsum[h]);
    __syncthreads();
    float inv[NH1];
#pragma unroll
    for (int h = 0; h < NH1; h++) inv[h] = 1.f / (ss[h] + 1e-16f);

    // phase B: weighted gather-accumulate (thread owns one channel)
    const int hh = t >> 6;
    float acc = 0.f;
    for (int base = start; base < end; base += CHUNK) {
        int cnt = min(CHUNK, end - base);
        __syncthreads();
        for (int i = t; i < cnt; i += 256) {
            int s = g_csr[base + i];
            ssrc[i] = s;
#pragma unroll
            for (int h = 0; h < NH1; h++)
                sal[i][h] = expf(lrelu(g_as1[s * 4 + h] + adv[h]) - mx[h]) * inv[h];
        }
        __syncthreads();
#pragma unroll 4
        for (int k = 0; k < cnt; k++)
            acc = fmaf(sal[k][hh], g_h1[(size_t)ssrc[k] * F1 + t], acc);
    }
    float v = acc + b1[t];
    g_hmid[(size_t)dst * F1 + t] = v > 0.f ? v : expm1f(v);  // fused elu
}

// ---------------- GEMM2: h2 = hmid @ W2  [50000,256]x[256,40] ----------------
#define BM2 128
#define BK2 32
__global__ __launch_bounds__(256) void k_gemm2(const float* __restrict__ W2) {
    __shared__ float As[BM2][BK2 + 4];
    __shared__ float Ws[BK2][F2];
    const int bm = blockIdx.x * BM2;
    const int t = threadIdx.x;
    const int tx = t & 7;    // 5 cols each
    const int ty = t >> 3;   // 4 rows each
    float acc[4][5];
#pragma unroll
    for (int i = 0; i < 4; i++)
#pragma unroll
        for (int j = 0; j < 5; j++) acc[i][j] = 0.f;

    for (int k0 = 0; k0 < F1; k0 += BK2) {
#pragma unroll
        for (int r = 0; r < 4; r++) {
            int f = t + r * 256;
            int row = f >> 3;
            int cv = (f & 7) * 4;
            float4 v = make_float4(0.f, 0.f, 0.f, 0.f);
            int gr = bm + row;
            if (gr < N_NODES) v = *(const float4*)&g_hmid[(size_t)gr * F1 + k0 + cv];
            *(float4*)&As[row][cv] = v;
        }
        for (int idx = t; idx < BK2 * F2; idx += 256) {
            int r = idx / F2, c = idx % F2;
            Ws[r][c] = W2[(size_t)(k0 + r) * F2 + c];
        }
        __syncthreads();
#pragma unroll
        for (int kk = 0; kk < BK2; kk++) {
            float a[4], b[5];
#pragma unroll
            for (int i = 0; i < 4; i++) a[i] = As[ty * 4 + i][kk];
#pragma unroll
            for (int j = 0; j < 5; j++) b[j] = Ws[kk][tx * 5 + j];
#pragma unroll
            for (int i = 0; i < 4; i++)
#pragma unroll
                for (int j = 0; j < 5; j++) acc[i][j] = fmaf(a[i], b[j], acc[i][j]);
        }
        __syncthreads();
    }
#pragma unroll
    for (int i = 0; i < 4; i++) {
        int gr = bm + ty * 4 + i;
        if (gr < N_NODES)
#pragma unroll
            for (int j = 0; j < 5; j++)
                g_h2[(size_t)gr * F2 + tx * 5 + j] = acc[i][j];
    }
}

// ---------------- attention coefficients layer 2 (warp per node) ----------------
__global__ void k_asd2(const float* __restrict__ atts, const float* __restrict__ attd) {
    int node = blockIdx.x * 8 + (threadIdx.x >> 5);
    int lane = threadIdx.x & 31;
    if (node >= N_NODES) return;
    const float* hr = &g_h2[(size_t)node * F2];
    float h0 = hr[lane];
    float vs = h0 * atts[lane];
    float vd = h0 * attd[lane];
    if (lane < 8) {
        float h1v = hr[32 + lane];
        vs += h1v * atts[32 + lane];
        vd += h1v * attd[32 + lane];
    }
#pragma unroll
    for (int off = 16; off; off >>= 1) {
        vs += __shfl_down_sync(0xffffffffu, vs, off);
        vd += __shfl_down_sync(0xffffffffu, vd, off);
    }
    if (lane == 0) { g_as2[node] = vs; g_ad2[node] = vd; }
}

// ---------------- layer-2 aggregation + bias + log_softmax ----------------
#define CHUNK2 256
__global__ __launch_bounds__(64) void k_agg2(const float* __restrict__ b2,
                                             float* __restrict__ out) {
    const int dst = blockIdx.x;
    const int t = threadIdx.x;
    const int start = g_rowstart[dst];
    const int end = g_rowstart[dst + 1];
    __shared__ float sal[CHUNK2];
    __shared__ int   ssrc[CHUNK2];
    __shared__ float sm, ssum, slog;
    __shared__ float sv[64];
    const float adv = g_ad2[dst];
    if (t == 0) { sm = NINF; ssum = 0.f; }
    __syncthreads();

    float lm = NINF;
    for (int i = start + t; i < end; i += 64)
        lm = fmaxf(lm, lrelu(g_as2[g_csr[i]] + adv));
    atomicMaxFloatS(&sm, lm);
    __syncthreads();
    const float mx = sm;

    float ls = 0.f;
    for (int i = start + t; i < end; i += 64)
        ls += expf(lrelu(g_as2[g_csr[i]] + adv) - mx);
    atomicAdd(&ssum, ls);
    __syncthreads();
    const float inv = 1.f / (ssum + 1e-16f);

    float acc = 0.f;
    for (int base = start; base < end; base += CHUNK2) {
        int cnt = min(CHUNK2, end - base);
        __syncthreads();
        for (int i = t; i < cnt; i += 64) {
            int s = g_csr[base + i];
            ssrc[i] = s;
            sal[i] = expf(lrelu(g_as2[s] + adv) - mx) * inv;
        }
        __syncthreads();
        if (t < F2) {
#pragma unroll 4
            for (int k = 0; k < cnt; k++)
                acc = fmaf(sal[k], g_h2[(size_t)ssrc[k] * F2 + t], acc);
        }
    }
    sv[t] = (t < F2) ? acc + b2[t] : NINF;
    __syncthreads();
    if (t == 0) {
        float m2 = NINF;
        for (int i = 0; i < F2; i++) m2 = fmaxf(m2, sv[i]);
        float se = 0.f;
        for (int i = 0; i < F2; i++) se += expf(sv[i] - m2);
        sm = m2;
        slog = logf(se);
    }
    __syncthreads();
    if (t < F2) out[(size_t)dst * F2 + t] = sv[t] - sm - slog;
}

// ---------------- launch ----------------
extern "C" void kernel_launch(void* const* d_in, const int* in_sizes, int n_in,
                              void* d_out, int out_size) {
    const float* x   = (const float*)d_in[0];
    const void*  ei  = d_in[1];
    const float* W1  = (const float*)d_in[2];
    const float* as1 = (const float*)d_in[3];
    const float* ad1 = (const float*)d_in[4];
    const float* b1  = (const float*)d_in[5];
    const float* W2  = (const float*)d_in[6];
    const float* as2 = (const float*)d_in[7];
    const float* ad2 = (const float*)d_in[8];
    const float* b2  = (const float*)d_in[9];
    float* out = (float*)d_out;

    k_detect<<<1, 1>>>((const int*)ei);
    k_convert<<<(E_EDGES + 255) / 256, 256>>>(ei);
    k_initdeg<<<(N_NODES + 255) / 256, 256>>>();
    k_count<<<(E_EDGES + 255) / 256, 256>>>();
    k_scan<<<1, 1024>>>();
    k_scatter<<<(E_TOT + 255) / 256, 256>>>();

    dim3 g1(F1 / BN, (N_NODES + BM - 1) / BM);
    k_gemm1<<<g1, 256>>>(x, W1);
    k_asd1<<<(N_NODES + 7) / 8, 256>>>(as1, ad1);
    k_agg1<<<N_NODES, 256>>>(b1);
    k_gemm2<<<(N_NODES + BM2 - 1) / BM2, 256>>>(W2);
    k_asd2<<<(N_NODES + 7) / 8, 256>>>(as2, ad2);
    k_agg2<<<N_NODES, 64>>>(b2, out);
}